// round 9
// baseline (speedup 1.0000x reference)
#include <cuda_runtime.h>

// out[i] = sum_j relu(adj[i,j] * Linv[i,j]) * W[j] + b
// N = 8192. Inputs: d_in[0]=x_e (unused), d_in[1]=Linv, d_in[2]=adjacency,
// d_in[3]=W (N floats), d_in[4]=b (1 float). Output: N floats ([N,1]).
//
// One row per warp: 8 warps/CTA, 1024 CTAs -> 8192 rows, single wave,
// no __syncthreads, no smem, warp-shuffle reduce only.

#define N_DIM 8192
#define THREADS 256
#define WARPS_PER_CTA (THREADS / 32)
#define F4_PER_ROW (N_DIM / 4)          // 2048
#define ITERS (F4_PER_ROW / 32)         // 64 per lane

__global__ __launch_bounds__(THREADS, 7)
void dist2cycle_warprow_kernel(const float4* __restrict__ Linv,
                               const float4* __restrict__ adj,
                               const float4* __restrict__ W4,
                               const float*  __restrict__ bptr,
                               float* __restrict__ out) {
    const int lane = threadIdx.x & 31;
    const int wid  = threadIdx.x >> 5;
    const int row  = blockIdx.x * WARPS_PER_CTA + wid;

    const size_t base = (size_t)row * F4_PER_ROW;
    const float4* __restrict__ L = Linv + base;
    const float4* __restrict__ A = adj  + base;

    float acc = 0.0f;

    // Each lane: 64 float4 at stride 32. Unroll 4 -> 8 stream LDG.128 in flight.
    #pragma unroll 4
    for (int j = lane; j < F4_PER_ROW; j += 32) {
        float4 l = __ldcs(&L[j]);
        float4 a = __ldcs(&A[j]);
        float4 w = __ldg(&W4[j]);
        acc = fmaf(fmaxf(a.x * l.x, 0.0f), w.x, acc);
        acc = fmaf(fmaxf(a.y * l.y, 0.0f), w.y, acc);
        acc = fmaf(fmaxf(a.z * l.z, 0.0f), w.z, acc);
        acc = fmaf(fmaxf(a.w * l.w, 0.0f), w.w, acc);
    }

    // Warp reduce — the only cross-thread communication in the kernel.
    #pragma unroll
    for (int off = 16; off > 0; off >>= 1)
        acc += __shfl_xor_sync(0xFFFFFFFFu, acc, off);

    if (lane == 0)
        out[row] = acc + __ldg(bptr);
}

extern "C" void kernel_launch(void* const* d_in, const int* in_sizes, int n_in,
                              void* d_out, int out_size) {
    // metadata order: x_e, Linv, adjacency, W, b
    const float4* Linv = (const float4*)d_in[1];
    const float4* adj  = (const float4*)d_in[2];
    const float4* W4   = (const float4*)d_in[3];
    const float*  b    = (const float*)d_in[4];
    float* out = (float*)d_out;

    dist2cycle_warprow_kernel<<<N_DIM / WARPS_PER_CTA, THREADS>>>(Linv, adj, W4, b, out);
}

// round 10
// speedup vs baseline: 1.1792x; 1.1792x over previous
#include <cuda_runtime.h>

// out[i] = sum_j relu(adj[i,j] * Linv[i,j]) * W[j] + b
// N = 8192. Inputs: d_in[0]=x_e (unused), d_in[1]=Linv, d_in[2]=adjacency,
// d_in[3]=W (N floats), d_in[4]=b (1 float). Output: N floats ([N,1]).
//
// Stage 1: 16384 CTAs, each reduces one HALF-row into g_partials[half][row].
// Stage 2: 8192 threads combine the two halves + bias. Deterministic, no atomics.

#define N_DIM 8192
#define THREADS 256
#define HALF_F4 (N_DIM / 4 / 2)   // 1024 float4 per half-row

__device__ float g_partials[2 * N_DIM];

__global__ __launch_bounds__(THREADS, 8)
void dist2cycle_halfrow_kernel(const float4* __restrict__ Linv,
                               const float4* __restrict__ adj,
                               const float4* __restrict__ W4) {
    const int row  = blockIdx.x >> 1;
    const int half = blockIdx.x & 1;

    const size_t base = (size_t)row * (N_DIM / 4) + (size_t)half * HALF_F4;
    const float4* __restrict__ L = Linv + base;
    const float4* __restrict__ A = adj  + base;
    const float4* __restrict__ W = W4 + (size_t)half * HALF_F4;

    float acc = 0.0f;

    // 1024 float4 over 256 threads -> 4 iterations.
    #pragma unroll 4
    for (int j = threadIdx.x; j < HALF_F4; j += THREADS) {
        float4 l = __ldcs(&L[j]);
        float4 a = __ldcs(&A[j]);
        float4 w = __ldg(&W[j]);
        acc = fmaf(fmaxf(a.x * l.x, 0.0f), w.x, acc);
        acc = fmaf(fmaxf(a.y * l.y, 0.0f), w.y, acc);
        acc = fmaf(fmaxf(a.z * l.z, 0.0f), w.z, acc);
        acc = fmaf(fmaxf(a.w * l.w, 0.0f), w.w, acc);
    }

    // Warp reduce
    #pragma unroll
    for (int off = 16; off > 0; off >>= 1)
        acc += __shfl_xor_sync(0xFFFFFFFFu, acc, off);

    // Block reduce across 8 warps
    __shared__ float warp_sums[THREADS / 32];
    const int lane = threadIdx.x & 31;
    const int wid  = threadIdx.x >> 5;
    if (lane == 0) warp_sums[wid] = acc;
    __syncthreads();

    if (wid == 0) {
        float v = (lane < THREADS / 32) ? warp_sums[lane] : 0.0f;
        #pragma unroll
        for (int off = 4; off > 0; off >>= 1)
            v += __shfl_xor_sync(0xFFFFFFFFu, v, off);
        if (lane == 0)
            g_partials[half * N_DIM + row] = v;
    }
}

__global__ __launch_bounds__(256)
void dist2cycle_combine_kernel(const float* __restrict__ bptr,
                               float* __restrict__ out) {
    const int i = blockIdx.x * blockDim.x + threadIdx.x;
    if (i < N_DIM)
        out[i] = g_partials[i] + g_partials[N_DIM + i] + __ldg(bptr);
}

extern "C" void kernel_launch(void* const* d_in, const int* in_sizes, int n_in,
                              void* d_out, int out_size) {
    // metadata order: x_e, Linv, adjacency, W, b
    const float4* Linv = (const float4*)d_in[1];
    const float4* adj  = (const float4*)d_in[2];
    const float4* W4   = (const float4*)d_in[3];
    const float*  b    = (const float*)d_in[4];
    float* out = (float*)d_out;

    dist2cycle_halfrow_kernel<<<2 * N_DIM, THREADS>>>(Linv, adj, W4);
    dist2cycle_combine_kernel<<<N_DIM / 256, 256>>>(b, out);
}

// round 11
// speedup vs baseline: 1.1854x; 1.0053x over previous
#include <cuda_runtime.h>

// out[i] = sum_j relu(adj[i,j] * Linv[i,j]) * W[j] + b
// N = 8192. Inputs: d_in[0]=x_e (unused), d_in[1]=Linv, d_in[2]=adjacency,
// d_in[3]=W (N floats), d_in[4]=b (1 float). Output: N floats ([N,1]).
//
// Single launch: 16384 CTAs, one per HALF-row (fine granularity -> good wave
// packing). Each CTA reduces its half; the second CTA to finish a row combines
// both halves + bias ("last block" threadfence pattern) and resets the flag,
// so state is clean for the next graph replay. Deterministic: the combine is
// always p0 + p1 + b in that order.

#define N_DIM 8192
#define THREADS 256
#define HALF_F4 (N_DIM / 4 / 2)   // 1024 float4 per half-row

__device__ float g_partials[2 * N_DIM];
__device__ int   g_flags[N_DIM];          // zero-init at load; reset after use

__global__ __launch_bounds__(THREADS, 8)
void dist2cycle_halfrow_fused_kernel(const float4* __restrict__ Linv,
                                     const float4* __restrict__ adj,
                                     const float4* __restrict__ W4,
                                     const float*  __restrict__ bptr,
                                     float* __restrict__ out) {
    const int row  = blockIdx.x >> 1;
    const int half = blockIdx.x & 1;

    const size_t base = (size_t)row * (N_DIM / 4) + (size_t)half * HALF_F4;
    const float4* __restrict__ L = Linv + base;
    const float4* __restrict__ A = adj  + base;
    const float4* __restrict__ W = W4 + (size_t)half * HALF_F4;

    float acc = 0.0f;

    // 1024 float4 over 256 threads -> 4 iterations.
    #pragma unroll 4
    for (int j = threadIdx.x; j < HALF_F4; j += THREADS) {
        float4 l = __ldcs(&L[j]);
        float4 a = __ldcs(&A[j]);
        float4 w = __ldg(&W[j]);
        acc = fmaf(fmaxf(a.x * l.x, 0.0f), w.x, acc);
        acc = fmaf(fmaxf(a.y * l.y, 0.0f), w.y, acc);
        acc = fmaf(fmaxf(a.z * l.z, 0.0f), w.z, acc);
        acc = fmaf(fmaxf(a.w * l.w, 0.0f), w.w, acc);
    }

    // Warp reduce
    #pragma unroll
    for (int off = 16; off > 0; off >>= 1)
        acc += __shfl_xor_sync(0xFFFFFFFFu, acc, off);

    // Block reduce across 8 warps
    __shared__ float warp_sums[THREADS / 32];
    __shared__ int   s_is_last;
    const int lane = threadIdx.x & 31;
    const int wid  = threadIdx.x >> 5;
    if (lane == 0) warp_sums[wid] = acc;
    __syncthreads();

    if (wid == 0) {
        float v = (lane < THREADS / 32) ? warp_sums[lane] : 0.0f;
        #pragma unroll
        for (int off = 4; off > 0; off >>= 1)
            v += __shfl_xor_sync(0xFFFFFFFFu, v, off);

        if (lane == 0) {
            // Publish this half's partial, then decide who combines.
            g_partials[2 * row + half] = v;
            __threadfence();
            int prev = atomicAdd(&g_flags[row], 1);
            if (prev == 1) {
                // We are second: other half's partial is visible (it fenced
                // before its atomic, and atomics on g_flags[row] serialize).
                volatile float* gp = g_partials;
                float p0 = gp[2 * row + 0];
                float p1 = gp[2 * row + 1];
                out[row] = p0 + p1 + __ldg(bptr);
                g_flags[row] = 0;   // reset for next graph replay
            }
        }
    }
}

extern "C" void kernel_launch(void* const* d_in, const int* in_sizes, int n_in,
                              void* d_out, int out_size) {
    // metadata order: x_e, Linv, adjacency, W, b
    const float4* Linv = (const float4*)d_in[1];
    const float4* adj  = (const float4*)d_in[2];
    const float4* W4   = (const float4*)d_in[3];
    const float*  b    = (const float*)d_in[4];
    float* out = (float*)d_out;

    dist2cycle_halfrow_fused_kernel<<<2 * N_DIM, THREADS>>>(Linv, adj, W4, b, out);
}